// round 10
// baseline (speedup 1.0000x reference)
#include <cuda_runtime.h>
#include <math.h>

#define BB 8
#define NN 256
#define DD 128
#define ROWS (BB*NN)          // 2048
#define EROWS (BB*NN*NN)      // 524288
#define BN_EPS 1e-5f
#define RPW 8                 // e-rows per warp per chunk
#define TI  4                 // i-rows per block's tail tile
#define NBLK 512              // persistent blocks (co-resident: 4/SM x 148)
#define NCHUNK 8192           // copy chunks (64 e-rows each)
#define CPB 1024              // chunks per batch

// __device__ globals: zero at load; reset at end of every launch by the last
// block through the exit barrier -> graph-replay safe.
__device__ float g_w[EROWS];
__device__ float g_Wt[DD*DD];
__device__ float g_sum[DD];
__device__ float g_sumsq[DD];
__device__ int   g_ticket;
__device__ int   g_done[BB];
__device__ int   g_wt_ready;
__device__ int   g_bar1;
__device__ int   g_bar2;

__global__ void __launch_bounds__(256, 4) k_all(
    const float* __restrict__ h,
    const float4* __restrict__ e,
    const float* __restrict__ Wm,
    const float* __restrict__ bias,
    const float* __restrict__ gamma,
    const float* __restrict__ beta,
    float* __restrict__ out_h,
    float4* __restrict__ out_e)
{
    const int bid  = blockIdx.x;
    const int tid  = threadIdx.x;
    const int warp = tid >> 5, lane = tid & 31;
    const int t    = tid & 127;       // feature index
    const int half = tid >> 7;        // 0/1: j-split in agg, row-split after

    __shared__ float sw[TI][NN];      // softmax probs (4 KB)
    __shared__ float sacc[2][TI][DD]; // per-half agg partials (4 KB)
    __shared__ float sx[TI][DD];      // pre-linear activations (2 KB)
    __shared__ float pp[DD], pps[DD]; // half-1 BN partials (1 KB)
    __shared__ int   s_t, s_ready, s_last;

    // --- block 0: transpose W, publish ready flag ---
    if (bid == 0) {
        for (int i = tid; i < DD*DD; i += 256) {
            int r = i >> 7, c = i & 127;
            g_Wt[c * DD + r] = Wm[i];       // coalesced read of W
        }
        __syncthreads();
        if (tid == 0) { __threadfence(); atomicExch(&g_wt_ready, 1); }
    }

    const int bi0 = bid * TI;         // this block's tail tile
    const int myb = bi0 >> 8;
    const int i0  = bi0 & 255;
    const float* hb = h + (size_t)myb * NN * DD;

    bool  tail_done = false;
    float yv[2], hres[2];             // survive until BN apply

    // =============== tail tile compute (inlined via lambda) ===============
    auto do_tail = [&]() {
        // softmax: warps 0-3, one row each
        if (warp < TI) {
            const float* wrow = g_w + (size_t)(bi0 + warp) * NN;
            float v[NN/32];
            float m = -1e30f;
            #pragma unroll
            for (int k = 0; k < NN/32; k++) {
                v[k] = wrow[lane + 32*k];
                m = fmaxf(m, v[k]);
            }
            #pragma unroll
            for (int o = 16; o > 0; o >>= 1)
                m = fmaxf(m, __shfl_xor_sync(0xffffffffu, m, o));
            float sum = 0.0f;
            #pragma unroll
            for (int k = 0; k < NN/32; k++) {
                v[k] = __expf(v[k] - m);
                sum += v[k];
            }
            #pragma unroll
            for (int o = 16; o > 0; o >>= 1)
                sum += __shfl_xor_sync(0xffffffffu, sum, o);
            float inv = 1.0f / sum;
            #pragma unroll
            for (int k = 0; k < NN/32; k++)
                sw[warp][lane + 32*k] = v[k] * inv;
        }
        __syncthreads();

        // agg: half owns j in [half*128, +128) for all 4 rows
        {
            float acc[TI] = {0.f, 0.f, 0.f, 0.f};
            int jbase = half * 128;
            for (int j0 = 0; j0 < 128; j0 += 16) {
                float hv[16];
                #pragma unroll
                for (int k = 0; k < 16; k++)
                    hv[k] = hb[(jbase + j0 + k) * DD + t];
                #pragma unroll
                for (int r = 0; r < TI; r++) {
                    const float4* swr = (const float4*)&sw[r][jbase + j0];
                    #pragma unroll
                    for (int q2 = 0; q2 < 4; q2++) {
                        float4 p = swr[q2];
                        acc[r] = fmaf(p.x, hv[q2*4+0], acc[r]);
                        acc[r] = fmaf(p.y, hv[q2*4+1], acc[r]);
                        acc[r] = fmaf(p.z, hv[q2*4+2], acc[r]);
                        acc[r] = fmaf(p.w, hv[q2*4+3], acc[r]);
                    }
                }
            }
            #pragma unroll
            for (int r = 0; r < TI; r++)
                sacc[half][r][t] = acc[r];
        }
        __syncthreads();

        // combine halves; half owns rows {2h, 2h+1}
        #pragma unroll
        for (int rr = 0; rr < 2; rr++) {
            int r = half * 2 + rr;
            hres[rr] = hb[(i0 + r) * DD + t];
            sx[r][t] = hres[rr] + sacc[0][r][t] + sacc[1][r][t];
        }
        __syncthreads();

        // linear via transposed W (coalesced) + relu
        float bt = bias[t];
        yv[0] = bt; yv[1] = bt;
        for (int d0 = 0; d0 < DD; d0 += 16) {
            float wt[16];
            #pragma unroll
            for (int k = 0; k < 16; k++)
                wt[k] = g_Wt[(d0 + k) * DD + t];
            #pragma unroll
            for (int rr = 0; rr < 2; rr++) {
                const float4* xr = (const float4*)&sx[half*2 + rr][d0];
                #pragma unroll
                for (int q2 = 0; q2 < 4; q2++) {
                    float4 xv = xr[q2];
                    yv[rr] = fmaf(xv.x, wt[q2*4+0], yv[rr]);
                    yv[rr] = fmaf(xv.y, wt[q2*4+1], yv[rr]);
                    yv[rr] = fmaf(xv.z, wt[q2*4+2], yv[rr]);
                    yv[rr] = fmaf(xv.w, wt[q2*4+3], yv[rr]);
                }
            }
        }
        float ls = 0.0f, lss = 0.0f;
        #pragma unroll
        for (int rr = 0; rr < 2; rr++) {
            yv[rr] = fmaxf(yv[rr], 0.0f);
            ls  += yv[rr];
            lss  = fmaf(yv[rr], yv[rr], lss);
        }
        if (half == 1) { pp[t] = ls; pps[t] = lss; }
        __syncthreads();
        if (half == 0) {
            atomicAdd(&g_sum[t],   ls  + pp[t]);
            atomicAdd(&g_sumsq[t], lss + pps[t]);
        }
        __syncthreads();
    };

    // ======================= main ticket loop ============================
    for (;;) {
        if (tid == 0) s_t = atomicAdd(&g_ticket, 1);
        __syncthreads();
        int c = s_t;

        // opportunistic tail interjection (overlaps with remaining copy)
        if (!tail_done) {
            if (tid == 0)
                s_ready = (atomicAdd(&g_wt_ready, 0) != 0) &&
                          (atomicAdd(&g_done[myb], 0) >= CPB);
            __syncthreads();
            if (s_ready) {
                __threadfence();
                do_tail();
                tail_done = true;
            }
            __syncthreads();
        }

        if (c >= NCHUNK) break;

        // copy chunk c: 64 e-rows, warp w handles rows c*64 + w*8 .. +8
        {
            size_t gwarp = (size_t)c * 8 + warp;
            size_t r0    = gwarp * RPW;
            size_t base  = r0 * 32 + lane;

            float4 v[RPW];
            #pragma unroll
            for (int k = 0; k < RPW; k++)
                v[k] = __ldcs(e + base + (size_t)k * 32);
            #pragma unroll
            for (int k = 0; k < RPW; k++)
                __stcs(out_e + base + (size_t)k * 32, v[k]);

            float s[RPW];
            #pragma unroll
            for (int k = 0; k < RPW; k++)
                s[k] = v[k].x*v[k].x + v[k].y*v[k].y + v[k].z*v[k].z + v[k].w*v[k].w;
            #pragma unroll
            for (int o = 16; o > 0; o >>= 1) {
                #pragma unroll
                for (int k = 0; k < RPW; k++)
                    s[k] += __shfl_xor_sync(0xffffffffu, s[k], o);
            }
            if (lane == 0) {
                #pragma unroll
                for (int k = 0; k < RPW; k++)
                    g_w[r0 + k] = sqrtf(s[k]);
            }
        }
        __syncthreads();
        if (tid == 0) { __threadfence(); atomicAdd(&g_done[c >> 10], 1); }
    }

    // leftover tail (mostly batch-7 owners)
    if (!tail_done) {
        if (tid == 0) {
            while (!((atomicAdd(&g_wt_ready, 0) != 0) &&
                     (atomicAdd(&g_done[myb], 0) >= CPB)))
                __nanosleep(128);
        }
        __syncthreads();
        __threadfence();
        do_tail();
    }

    // grid barrier 1 (all 512 blocks co-resident by launch_bounds(256,4))
    __syncthreads();
    if (tid == 0) {
        __threadfence();
        atomicAdd(&g_bar1, 1);
        while (atomicAdd(&g_bar1, 0) < NBLK) __nanosleep(64);
    }
    __syncthreads();
    __threadfence();

    // BN apply + residual straight from registers
    {
        float s  = __ldcg(&g_sum[t]);
        float ss = __ldcg(&g_sumsq[t]);
        float mean = s * (1.0f / ROWS);
        float var  = ss * (1.0f / ROWS) - mean * mean;
        float g  = gamma[t] * rsqrtf(var + BN_EPS);
        float b2 = beta[t] - mean * g;
        #pragma unroll
        for (int rr = 0; rr < 2; rr++) {
            int r = half * 2 + rr;
            out_h[(bi0 + r) * DD + t] = fmaf(yv[rr], g, b2) + hres[rr];
        }
    }

    // exit barrier: last block through resets all state for the next replay
    __syncthreads();
    if (tid == 0) s_last = (atomicAdd(&g_bar2, 1) == NBLK - 1);
    __syncthreads();
    if (s_last) {
        for (int i = tid; i < DD; i += 256) { g_sum[i] = 0.0f; g_sumsq[i] = 0.0f; }
        if (tid < BB) g_done[tid] = 0;
        if (tid == 0) {
            g_ticket = 0; g_wt_ready = 0; g_bar1 = 0; g_bar2 = 0;
            __threadfence();
        }
    }
}

// ---------------------------------------------------------------------------
extern "C" void kernel_launch(void* const* d_in, const int* in_sizes, int n_in,
                              void* d_out, int out_size) {
    const float* h     = (const float*)d_in[0];   // (8,256,128)
    const float* e     = (const float*)d_in[1];   // (8,256,256,128)
    const float* Wm    = (const float*)d_in[2];   // (128,128)
    const float* bias  = (const float*)d_in[3];   // (128)
    const float* gamma = (const float*)d_in[4];   // (128)
    const float* beta  = (const float*)d_in[5];   // (128)

    float* out_h = (float*)d_out;                 // (8,256,128) first
    float* out_e = out_h + (size_t)ROWS * DD;     // then (8,256,256,128)

    k_all<<<NBLK, 256>>>(h, (const float4*)e, Wm, bias, gamma, beta,
                         out_h, (float4*)out_e);
}